// round 17
// baseline (speedup 1.0000x reference)
#include <cuda_runtime.h>
#include <cstdint>

// MultiBackScatter: three chained scatter-adds with UNIQUE (permutation) indices.
// Composition: out[idx0[idx1[idx2[i]]]] = x[i]; all other rows zero.
//
// R17: ONE kernel, one grid barrier:
//   A: each thread gathers up to 4 scatter chunks (chase + x float4) into REGS
//   B: pure zero sweep of the 410MB output (R1's 6.9TB/s pattern; A's load
//      latency hides under it)
//   C: single self-made grid barrier (monotonic counter -> replay-safe with no
//      reset; all blocks co-resident by construction), then register-sourced
//      scatter stores (no loads).
// Host sizes the grid from the occupancy API so co-residency is guaranteed
// (no deadlock); if <391 co-resident blocks, falls back to the proven R13
// path (memset node + inline-chase scatter).

#define NCHUNK_MAX 400000     // 25000 rows * 16 float4 chunks
#define MAXG 4

__device__ unsigned g_bar;    // monotonic barrier counter (never reset)

__global__ void __launch_bounds__(256) fused_kernel(
        const float4* __restrict__ x,
        const int* __restrict__ idx0,
        const int* __restrict__ idx1,
        const int* __restrict__ idx2,
        float4* __restrict__ out,
        int n4, int nchunks) {
    int tid = threadIdx.x;
    int t = blockIdx.x * 256 + tid;
    int total = gridDim.x * 256;

    // ---- Phase A: gather chase targets + x payload into registers ----
    float4 val[MAXG];
    int dst[MAXG];            // float4 index < 25.6M, fits int; -1 = unused
#pragma unroll
    for (int u = 0; u < MAXG; u++) {
        int c = t + u * total;
        dst[u] = -1;
        if (c < nchunks) {
            int row = c >> 4;
            int lane = c & 15;
            int j = __ldg(&idx2[row]);
            int k = __ldg(&idx1[j]);
            int m = __ldg(&idx0[k]);
            val[u] = __ldg(&x[(long long)row * 16 + lane]);
            dst[u] = m * 16 + lane;
        }
    }

    // ---- Phase B: pure zero sweep (no loads in the store stream) ----
    const float4 z = make_float4(0.f, 0.f, 0.f, 0.f);
    for (int i = t; i < n4; i += total) {
        out[i] = z;
    }

    // ---- single grid barrier (monotonic epochs; no reset across replays) ----
    __threadfence();                      // release my zero stores
    __syncthreads();                      // block done sweeping
    if (tid == 0) {
        unsigned my = atomicAdd(&g_bar, 1u);
        unsigned target = my - (my % gridDim.x) + gridDim.x;
        unsigned cur;
        do {
            asm volatile("ld.acquire.gpu.u32 %0, [%1];"
                         : "=r"(cur) : "l"(&g_bar) : "memory");
            if (cur >= target) break;
            __nanosleep(64);
        } while (true);
    }
    __syncthreads();                      // all zeros globally visible

    // ---- Phase C: register-sourced scatter stores (no loads) ----
#pragma unroll
    for (int u = 0; u < MAXG; u++) {
        if (dst[u] >= 0) {
            out[dst[u]] = val[u];
        }
    }
}

// Fallback path (R13): memset node + inline-chase scatter.
__global__ void __launch_bounds__(256) scatter_kernel(
        const float4* __restrict__ x,
        const int* __restrict__ idx0,
        const int* __restrict__ idx1,
        const int* __restrict__ idx2,
        float4* __restrict__ out,
        int n_rows) {
    int t = blockIdx.x * 256 + threadIdx.x;
    int row = t >> 4;
    int lane = t & 15;
    if (row >= n_rows) return;
    int j = __ldg(&idx2[row]);
    int k = __ldg(&idx1[j]);
    int m = __ldg(&idx0[k]);
    out[(long long)m * 16 + lane] = __ldg(&x[(long long)row * 16 + lane]);
}

extern "C" void kernel_launch(void* const* d_in, const int* in_sizes, int n_in,
                              void* d_out, int out_size) {
    const float* x   = (const float*)d_in[0];
    const int* idx0  = (const int*)d_in[1];
    const int* idx1  = (const int*)d_in[2];
    const int* idx2  = (const int*)d_in[3];
    float* out       = (float*)d_out;

    const int F = 64;
    int n_rows = in_sizes[0] / F;            // 25000
    int n4 = out_size / 4;                   // 25.6M float4
    int nchunks = n_rows * 16;               // 400000

    // size grid for guaranteed co-residency (deterministic per device)
    int nb = 0, nsm = 0;
    cudaOccupancyMaxActiveBlocksPerMultiprocessor(&nb, fused_kernel, 256, 0);
    cudaDeviceGetAttribute(&nsm, cudaDevAttrMultiProcessorCount, 0);
    long long grid = (long long)nb * nsm;
    if (grid > 888) grid = 888;              // cap: sweep saturates well below this

    if (grid * 256 * MAXG >= nchunks) {
        fused_kernel<<<(int)grid, 256>>>((const float4*)x, idx0, idx1, idx2,
                                         (float4*)out, n4, nchunks);
    } else {
        // fallback: proven R13 (64.0us)
        cudaMemsetAsync(d_out, 0, (size_t)out_size * sizeof(float), 0);
        int blocks = (nchunks + 255) / 256;
        scatter_kernel<<<blocks, 256>>>((const float4*)x, idx0, idx1, idx2,
                                        (float4*)out, n_rows);
    }
}